// round 5
// baseline (speedup 1.0000x reference)
#include <cuda_runtime.h>

#define FEAT 39
#define HID 1024
#define SEQ 254
#define NCLS 10
#define FC1N 100
#define BATCH 128

// Scratch (device globals; no allocation allowed).
__device__ float g_seq[SEQ * BATCH * HID];    // xproj then h_s, in place
__device__ float g_part[SEQ * BATCH * FC1N];  // FC1 split-K partials
__device__ float g_h1[BATCH * FC1N];

// ---------------- packed f32x2 + smem helpers ----------------
__device__ __forceinline__ unsigned smem_u32(const void* p) {
    return (unsigned)__cvta_generic_to_shared(p);
}
__device__ __forceinline__ void unpack2(unsigned long long v, float& lo, float& hi) {
    asm("mov.b64 {%0, %1}, %2;" : "=f"(lo), "=f"(hi) : "l"(v));
}
__device__ __forceinline__ void fma2(unsigned long long& d, unsigned long long a,
                                     unsigned long long b) {
    asm("fma.rn.f32x2 %0, %1, %2, %0;" : "+l"(d) : "l"(a), "l"(b));
}
__device__ __forceinline__ unsigned long long lds64(unsigned addr) {
    unsigned long long r;
    asm volatile("ld.shared.b64 %0, [%1];" : "=l"(r) : "r"(addr));
    return r;
}
__device__ __forceinline__ void cpasync16(unsigned dst, const void* src) {
    asm volatile("cp.async.cg.shared.global [%0], [%1], 16;" ::"r"(dst), "l"(src));
}
__device__ __forceinline__ void cp_commit() {
    asm volatile("cp.async.commit_group;");
}
template <int N>
__device__ __forceinline__ void cp_wait() {
    asm volatile("cp.async.wait_group %0;" ::"n"(N));
}

// ---------------- kernel 1: xproj = x @ W_ih^T + b_ih + b_hh, time-major ----------------
#define XP_BM 64
#define XP_BN 64
#define XP_PAD 41
__global__ __launch_bounds__(256) void xproj_kernel(
    const float* __restrict__ x, const float* __restrict__ Wih,
    const float* __restrict__ bih, const float* __restrict__ bhh) {
    __shared__ float Xs[XP_BM][XP_PAD];
    __shared__ float Ws[XP_BN][XP_PAD];
    int t = threadIdx.x;
    int n0 = blockIdx.x * XP_BN;
    int r0 = blockIdx.y * XP_BM;

    for (int i = t; i < XP_BM * FEAT; i += 256) {
        int row = i / FEAT, col = i % FEAT;
        int r = r0 + row;
        int b = r & (BATCH - 1), s = r >> 7;
        Xs[row][col] = x[((size_t)b * SEQ + s) * FEAT + col];
    }
    for (int i = t; i < XP_BN * FEAT; i += 256) {
        int row = i / FEAT, col = i % FEAT;
        Ws[row][col] = Wih[(size_t)(n0 + row) * FEAT + col];
    }
    __syncthreads();

    int tn = t & 15, tm = t >> 4;
    float acc[4][4] = {};
#pragma unroll
    for (int k = 0; k < FEAT; k++) {
        float a[4], w[4];
#pragma unroll
        for (int i = 0; i < 4; i++) a[i] = Xs[tm * 4 + i][k];
#pragma unroll
        for (int j = 0; j < 4; j++) w[j] = Ws[tn * 4 + j][k];
#pragma unroll
        for (int i = 0; i < 4; i++)
#pragma unroll
            for (int j = 0; j < 4; j++) acc[i][j] += a[i] * w[j];
    }
#pragma unroll
    for (int j = 0; j < 4; j++) {
        int n = n0 + tn * 4 + j;
        float bias = bih[n] + bhh[n];
#pragma unroll
        for (int i = 0; i < 4; i++) {
            int r = r0 + tm * 4 + i;
            g_seq[(size_t)r * HID + n] = acc[i][j] + bias;
        }
    }
}

// ---------------- kernel 2: recurrence step — 16 warps, warp-private pipeline ----------------
// out[m][n] = tanh(xp[m][n] + sum_k H[m][k]*Whh[n][k])
// 128 blocks (32 ngrp x 4 mgrp), 16 warps (512 thr). Warp kg owns the
// contiguous k-slice [kg*64, kg*64+64), processed as 4 chunks of 16 k.
// Each warp stages its OWN 32x16 A and W tiles (2-deep cp.async ring):
// no block barriers in the mainloop; 4 warps/SMSP hide LDS/issue latency.
// Accumulators packed over (k even, k odd) -> pure natural lds64 + fma2.
#define AW_STRIDE 20                   // floats per tile row (16B-aligned, bank-spread)
#define TILE_F (32 * AW_STRIDE)        // 640 floats per tile
#define WARP_REGION (4 * TILE_F)       // 2 buffers x (A + W)
#define ST_SMEM (16 * WARP_REGION * 4) // 163840 bytes

__global__ __launch_bounds__(512) void step_kernel(
    int s, const float* __restrict__ h0, const float* __restrict__ Whh) {
    extern __shared__ float sm[];
    const float* Hp = (s == 0) ? h0 : (g_seq + (size_t)(s - 1) * BATCH * HID);
    float* out = g_seq + (size_t)s * BATCH * HID;

    int t = threadIdx.x;
    int n0 = blockIdx.x * 32;
    int m0 = blockIdx.y * 32;
    int kg = t >> 5;       // warp id = k-group (0..15)
    int lane = t & 31;
    int thrm = lane >> 2;  // 0..7
    int thrn = lane & 3;   // 0..3

    unsigned smBase = smem_u32(sm);
    unsigned warpBase = smBase + (unsigned)(kg * WARP_REGION) * 4u;

    int srow0 = lane >> 2, sc4 = lane & 3;  // 8 rows x 4 float4 per tile pass

    auto stage = [&](int c, int b) {
        unsigned dstA = warpBase + (unsigned)(b * 2 * TILE_F) * 4u;
        unsigned dstW = dstA + (unsigned)TILE_F * 4u;
        int koff = kg * 64 + c * 16 + sc4 * 4;
#pragma unroll
        for (int q = 0; q < 4; q++) {
            int row = srow0 + 8 * q;
            unsigned so = (unsigned)(row * AW_STRIDE + sc4 * 4) * 4u;
            cpasync16(dstA + so, Hp + (size_t)(m0 + row) * HID + koff);
            cpasync16(dstW + so, Whh + (size_t)(n0 + row) * HID + koff);
        }
        cp_commit();
    };

    unsigned long long acc[4][8];
#pragma unroll
    for (int i = 0; i < 4; i++)
#pragma unroll
        for (int j = 0; j < 8; j++) acc[i][j] = 0ull;

    unsigned aOff[4], wOff[8];
#pragma unroll
    for (int i = 0; i < 4; i++) aOff[i] = (unsigned)((thrm + 8 * i) * AW_STRIDE) * 4u;
#pragma unroll
    for (int j = 0; j < 8; j++) wOff[j] = (unsigned)((thrn + 4 * j) * AW_STRIDE) * 4u;

    auto compute = [&](int b) {
        unsigned aB = warpBase + (unsigned)(b * 2 * TILE_F) * 4u;
        unsigned wB = aB + (unsigned)TILE_F * 4u;
#pragma unroll
        for (int kp = 0; kp < 8; kp++) {
            unsigned kByte = (unsigned)kp * 8u;
            unsigned long long a[4], w[8];
#pragma unroll
            for (int i = 0; i < 4; i++) a[i] = lds64(aB + aOff[i] + kByte);
#pragma unroll
            for (int j = 0; j < 8; j++) w[j] = lds64(wB + wOff[j] + kByte);
#pragma unroll
            for (int i = 0; i < 4; i++)
#pragma unroll
                for (int j = 0; j < 8; j++) fma2(acc[i][j], a[i], w[j]);
        }
    };

    // warp-local 2-deep pipeline over 4 chunks; no block barriers
    stage(0, 0);
    stage(1, 1);
    cp_wait<1>();
    __syncwarp();
    compute(0);
    stage(2, 0);
    cp_wait<1>();
    __syncwarp();
    compute(1);
    stage(3, 1);
    cp_wait<1>();
    __syncwarp();
    compute(0);
    cp_wait<0>();
    __syncwarp();
    compute(1);

    __syncthreads();  // all warps done before reusing smem for reduction

    // epilogue: collapse k-even/odd, reduce 16 warp-partials, tanh
    float* Rs = sm;  // [16][32][33] floats = 67584 B (aliases tile buffers)
#pragma unroll
    for (int i = 0; i < 4; i++) {
        int m = thrm + 8 * i;
#pragma unroll
        for (int j = 0; j < 8; j++) {
            int n = thrn + 4 * j;
            float lo, hi;
            unpack2(acc[i][j], lo, hi);
            Rs[(kg * 32 + m) * 33 + n] = lo + hi;
        }
    }
    __syncthreads();
#pragma unroll
    for (int u = 0; u < 2; u++) {
        int idx = t + u * 512;           // n spans all 32 banks per warp
        int m = idx >> 5, n = idx & 31;
        float sum = 0.0f;
#pragma unroll
        for (int g = 0; g < 16; g++) sum += Rs[(g * 32 + m) * 33 + n];
        size_t o = (size_t)(m0 + m) * HID + (n0 + n);
        out[o] = tanhf(out[o] + sum);
    }
}

// ---------------- kernel 3: FC1 split-K partials (fma2, batch-pair packed) ----------------
__global__ __launch_bounds__(256) void fc1_kernel(const float* __restrict__ W1) {
    __shared__ float Hs[32][130];   // transposed [k][b], 64-bit loads over b-pairs
    __shared__ float2 Wp[FC1N][34]; // duplicated {w,w} pairs for fma2
    int s = blockIdx.x;
    int t = threadIdx.x;
    const float* src = g_seq + (size_t)s * BATCH * HID;
    int tb = t & 63, tf = t >> 6;  // tb: batch-pair, tf: f-group of 25

    unsigned long long acc[25];
#pragma unroll
    for (int j = 0; j < 25; j++) acc[j] = 0ull;

    unsigned hBase = smem_u32(&Hs[0][0]) + (unsigned)(2 * tb) * 4u;
    unsigned wBase = smem_u32(&Wp[0][0]) + (unsigned)(tf * 25) * 34u * 8u;

    for (int k0 = 0; k0 < HID; k0 += 32) {
#pragma unroll
        for (int q = 0; q < 4; q++) {
            int f4 = t + q * 256;
            int row = f4 >> 3, c4 = f4 & 7;
            float4 v = *(const float4*)(src + (size_t)row * HID + k0 + c4 * 4);
            Hs[c4 * 4 + 0][row] = v.x;
            Hs[c4 * 4 + 1][row] = v.y;
            Hs[c4 * 4 + 2][row] = v.z;
            Hs[c4 * 4 + 3][row] = v.w;
        }
        for (int f4 = t; f4 < FC1N * 8; f4 += 256) {
            int row = f4 >> 3, c4 = f4 & 7;
            float4 v = *(const float4*)(W1 + (size_t)row * (SEQ * HID) + (size_t)s * HID +
                                        k0 + c4 * 4);
            Wp[row][c4 * 4 + 0] = make_float2(v.x, v.x);
            Wp[row][c4 * 4 + 1] = make_float2(v.y, v.y);
            Wp[row][c4 * 4 + 2] = make_float2(v.z, v.z);
            Wp[row][c4 * 4 + 3] = make_float2(v.w, v.w);
        }
        __syncthreads();
#pragma unroll 4
        for (int k = 0; k < 32; k++) {
            unsigned long long h2 = lds64(hBase + (unsigned)(k * 130) * 4u);
#pragma unroll
            for (int j = 0; j < 25; j++) {
                unsigned long long wv = lds64(wBase + (unsigned)(j * 34 + k) * 8u);
                fma2(acc[j], h2, wv);
            }
        }
        __syncthreads();
    }
    float* dst = g_part + (size_t)s * BATCH * FC1N;
#pragma unroll
    for (int j = 0; j < 25; j++) {
        float lo, hi;
        unpack2(acc[j], lo, hi);
        dst[(size_t)(2 * tb) * FC1N + tf * 25 + j] = lo;
        dst[(size_t)(2 * tb + 1) * FC1N + tf * 25 + j] = hi;
    }
}

// ---------------- kernel 4: deterministic reduce + bias + relu ----------------
__global__ __launch_bounds__(256) void reduce_kernel(const float* __restrict__ b1) {
    int i = blockIdx.x * 256 + threadIdx.x;
    if (i >= BATCH * FC1N) return;
    int f = i % FC1N;
    float p0 = 0.0f, p1 = 0.0f;
    for (int s = 0; s < SEQ; s += 2) {
        p0 += g_part[(size_t)s * BATCH * FC1N + i];
        p1 += g_part[(size_t)(s + 1) * BATCH * FC1N + i];
    }
    g_h1[i] = fmaxf(b1[f] + p0 + p1, 0.0f);
}

// ---------------- kernel 5: FC2 + log_softmax ----------------
__global__ __launch_bounds__(128) void fc2_kernel(const float* __restrict__ W2,
                                                  const float* __restrict__ b2,
                                                  float* __restrict__ out) {
    __shared__ float sW2[NCLS * FC1N];
    int t = threadIdx.x;
    for (int i = t; i < NCLS * FC1N; i += 128) sW2[i] = W2[i];
    __syncthreads();

    float hv[FC1N];
#pragma unroll
    for (int f = 0; f < FC1N; f++) hv[f] = g_h1[(size_t)t * FC1N + f];

    float logits[NCLS];
#pragma unroll
    for (int c = 0; c < NCLS; c++) {
        float acc = b2[c];
#pragma unroll
        for (int f = 0; f < FC1N; f++) acc += hv[f] * sW2[c * FC1N + f];
        logits[c] = acc;
    }
    float m = logits[0];
#pragma unroll
    for (int c = 1; c < NCLS; c++) m = fmaxf(m, logits[c]);
    float sum = 0.0f;
#pragma unroll
    for (int c = 0; c < NCLS; c++) sum += expf(logits[c] - m);
    float lse = m + logf(sum);
#pragma unroll
    for (int c = 0; c < NCLS; c++) out[(size_t)t * NCLS + c] = logits[c] - lse;
}

// ---------------- launch ----------------
extern "C" void kernel_launch(void* const* d_in, const int* in_sizes, int n_in,
                              void* d_out, int out_size) {
    const float* x = (const float*)d_in[0];
    const float* h0 = (const float*)d_in[1];
    const float* Wih = (const float*)d_in[2];
    const float* Whh = (const float*)d_in[3];
    const float* bih = (const float*)d_in[4];
    const float* bhh = (const float*)d_in[5];
    const float* W1 = (const float*)d_in[6];
    const float* b1 = (const float*)d_in[7];
    const float* W2 = (const float*)d_in[8];
    const float* b2 = (const float*)d_in[9];
    float* out = (float*)d_out;
    (void)in_sizes; (void)n_in; (void)out_size;

    cudaFuncSetAttribute(step_kernel, cudaFuncAttributeMaxDynamicSharedMemorySize,
                         ST_SMEM);

    xproj_kernel<<<dim3(HID / XP_BN, (SEQ * BATCH) / XP_BM), 256>>>(x, Wih, bih, bhh);
    for (int s = 0; s < SEQ; s++)
        step_kernel<<<dim3(32, 4), 512, ST_SMEM>>>(s, h0, Whh);
    fc1_kernel<<<SEQ, 256>>>(W1);
    reduce_kernel<<<(BATCH * FC1N + 255) / 256, 256>>>(b1);
    fc2_kernel<<<1, 128>>>(W2, b2, out);
}

// round 6
// speedup vs baseline: 1.0581x; 1.0581x over previous
#include <cuda_runtime.h>

#define FEAT 39
#define HID 1024
#define SEQ 254
#define NCLS 10
#define FC1N 100
#define BATCH 128

// Scratch (device globals; no allocation allowed).
__device__ float g_seq[SEQ * BATCH * HID];    // xproj then h_s, in place
__device__ float g_part[SEQ * BATCH * FC1N];  // FC1 split-K partials
__device__ float g_h1[BATCH * FC1N];
__device__ unsigned g_bar[4];                 // per-m-group step barriers

// ---------------- packed f32x2 + smem helpers ----------------
__device__ __forceinline__ unsigned smem_u32(const void* p) {
    return (unsigned)__cvta_generic_to_shared(p);
}
__device__ __forceinline__ void unpack2(unsigned long long v, float& lo, float& hi) {
    asm("mov.b64 {%0, %1}, %2;" : "=f"(lo), "=f"(hi) : "l"(v));
}
__device__ __forceinline__ void fma2(unsigned long long& d, unsigned long long a,
                                     unsigned long long b) {
    asm("fma.rn.f32x2 %0, %1, %2, %0;" : "+l"(d) : "l"(a), "l"(b));
}
__device__ __forceinline__ unsigned long long lds64(unsigned addr) {
    unsigned long long r;
    asm volatile("ld.shared.b64 %0, [%1];" : "=l"(r) : "r"(addr));
    return r;
}
__device__ __forceinline__ void cpasync16(unsigned dst, const void* src) {
    asm volatile("cp.async.cg.shared.global [%0], [%1], 16;" ::"r"(dst), "l"(src));
}
__device__ __forceinline__ void cp_commit() {
    asm volatile("cp.async.commit_group;");
}
template <int N>
__device__ __forceinline__ void cp_wait() {
    asm volatile("cp.async.wait_group %0;" ::"n"(N));
}

// ---------------- kernel 1: xproj = x @ W_ih^T + b_ih + b_hh, time-major ----------------
#define XP_BM 64
#define XP_BN 64
#define XP_PAD 41
__global__ __launch_bounds__(256) void xproj_kernel(
    const float* __restrict__ x, const float* __restrict__ Wih,
    const float* __restrict__ bih, const float* __restrict__ bhh) {
    __shared__ float Xs[XP_BM][XP_PAD];
    __shared__ float Ws[XP_BN][XP_PAD];
    int t = threadIdx.x;
    int n0 = blockIdx.x * XP_BN;
    int r0 = blockIdx.y * XP_BM;

    if (blockIdx.x == 0 && blockIdx.y == 0 && t < 4) g_bar[t] = 0u;  // reset step barriers

    for (int i = t; i < XP_BM * FEAT; i += 256) {
        int row = i / FEAT, col = i % FEAT;
        int r = r0 + row;
        int b = r & (BATCH - 1), s = r >> 7;
        Xs[row][col] = x[((size_t)b * SEQ + s) * FEAT + col];
    }
    for (int i = t; i < XP_BN * FEAT; i += 256) {
        int row = i / FEAT, col = i % FEAT;
        Ws[row][col] = Wih[(size_t)(n0 + row) * FEAT + col];
    }
    __syncthreads();

    int tn = t & 15, tm = t >> 4;
    float acc[4][4] = {};
#pragma unroll
    for (int k = 0; k < FEAT; k++) {
        float a[4], w[4];
#pragma unroll
        for (int i = 0; i < 4; i++) a[i] = Xs[tm * 4 + i][k];
#pragma unroll
        for (int j = 0; j < 4; j++) w[j] = Ws[tn * 4 + j][k];
#pragma unroll
        for (int i = 0; i < 4; i++)
#pragma unroll
            for (int j = 0; j < 4; j++) acc[i][j] += a[i] * w[j];
    }
#pragma unroll
    for (int j = 0; j < 4; j++) {
        int n = n0 + tn * 4 + j;
        float bias = bih[n] + bhh[n];
#pragma unroll
        for (int i = 0; i < 4; i++) {
            int r = r0 + tm * 4 + i;
            g_seq[(size_t)r * HID + n] = acc[i][j] + bias;
        }
    }
}

// ---------------- kernel 2: PERSISTENT recurrence scan ----------------
// 128 blocks = (32 n-groups) x (4 m-groups), 256 threads, all resident (1/SM).
// W slice [n0:n0+32][0:1024] lives in smem for the whole kernel.
// Per step: warp kg computes partials over k-slice [kg*128, kg*128+128),
// staging only H chunks (32m x 32k) via a 2-deep warp-private cp.async ring.
// Cross-block sync: per-m-group monotonic atomic barrier (32 blocks each).
#define AW_STRIDE 36
#define HTILE_F (32 * AW_STRIDE)    // 1152 floats per H chunk tile
#define H_RING_F (2 * HTILE_F)      // per-warp double buffer
#define W_STRIDE 1032               // 1032 % 32 == 8 -> conflict-free n-rows
#define W_REGION_F (32 * W_STRIDE)  // 33024 floats = 132096 B
#define PK_SMEM ((W_REGION_F + 8 * H_RING_F) * 4)  // 205824 B

__global__ __launch_bounds__(256) void rnn_persist(const float* __restrict__ h0,
                                                   const float* __restrict__ Whh) {
    extern __shared__ float sm[];
    int t = threadIdx.x;
    int n0 = blockIdx.x * 32;  // n-group 0..31
    int mi = blockIdx.y;       // m-group 0..3
    int m0 = mi * 32;
    int kg = t >> 5;           // warp 0..7 owns k-slice [kg*128, kg*128+128)
    int lane = t & 31;
    int thrm = lane >> 2;      // 0..7
    int thrn = lane & 3;       // 0..3
    int srow0 = lane >> 2, sc4 = lane & 3;

    unsigned smBase = smem_u32(sm);
    unsigned hBase = smBase + (unsigned)(W_REGION_F + kg * H_RING_F) * 4u;

    // Load resident W slice (rows = n, natural k layout, padded stride).
    for (int i = t * 4; i < 32 * 1024; i += 1024) {
        int row = i >> 10, col = i & 1023;
        float4 v = *(const float4*)(Whh + (size_t)(n0 + row) * HID + col);
        *(float4*)(sm + row * W_STRIDE + col) = v;
    }
    __syncthreads();

    unsigned aOff[4], wOff[8];
#pragma unroll
    for (int i = 0; i < 4; i++) aOff[i] = (unsigned)((thrm + 8 * i) * AW_STRIDE) * 4u;
#pragma unroll
    for (int j = 0; j < 8; j++) wOff[j] = (unsigned)((thrn + 4 * j) * W_STRIDE) * 4u;

    float* Rs = sm + W_REGION_F;  // [8][32][33] reduction scratch (aliases H ring)

    for (int s = 0; s < SEQ; s++) {
        const float* Hp = (s == 0) ? h0 : (g_seq + (size_t)(s - 1) * BATCH * HID);
        float* outp = g_seq + (size_t)s * BATCH * HID;

        auto stage = [&](int c, int b) {
            unsigned dst = hBase + (unsigned)(b * HTILE_F) * 4u;
            int kbase = kg * 128 + c * 32;
#pragma unroll
            for (int q = 0; q < 8; q++) {
                int row = srow0 + 8 * (q & 3);
                int c4 = sc4 + 4 * (q >> 2);
                unsigned so = (unsigned)(row * AW_STRIDE + c4 * 4) * 4u;
                cpasync16(dst + so, Hp + (size_t)(m0 + row) * HID + kbase + c4 * 4);
            }
            cp_commit();
        };

        unsigned long long acc[4][8];
#pragma unroll
        for (int i = 0; i < 4; i++)
#pragma unroll
            for (int j = 0; j < 8; j++) acc[i][j] = 0ull;

        auto compute = [&](int c, int b) {
            unsigned hB = hBase + (unsigned)(b * HTILE_F) * 4u;
            unsigned wK = smBase + (unsigned)((kg * 128 + c * 32)) * 4u;
#pragma unroll
            for (int kp = 0; kp < 16; kp++) {
                unsigned kByte = (unsigned)kp * 8u;
                unsigned long long a[4], w[8];
#pragma unroll
                for (int i = 0; i < 4; i++) a[i] = lds64(hB + aOff[i] + kByte);
#pragma unroll
                for (int j = 0; j < 8; j++) w[j] = lds64(wK + wOff[j] + kByte);
#pragma unroll
                for (int i = 0; i < 4; i++)
#pragma unroll
                    for (int j = 0; j < 8; j++) fma2(acc[i][j], a[i], w[j]);
            }
        };

        // warp-private 2-deep pipeline over 4 H chunks (no block barriers)
        stage(0, 0);
        stage(1, 1);
        cp_wait<1>();
        __syncwarp();
        compute(0, 0);
        stage(2, 0);
        cp_wait<1>();
        __syncwarp();
        compute(1, 1);
        stage(3, 1);
        cp_wait<1>();
        __syncwarp();
        compute(2, 0);
        cp_wait<0>();
        __syncwarp();
        compute(3, 1);

        __syncthreads();  // all warps done with H ring before aliasing as Rs

        // collapse k-even/odd, write warp partials
#pragma unroll
        for (int i = 0; i < 4; i++) {
            int m = thrm + 8 * i;
#pragma unroll
            for (int j = 0; j < 8; j++) {
                int n = thrn + 4 * j;
                float lo, hi;
                unpack2(acc[i][j], lo, hi);
                Rs[(kg * 32 + m) * 33 + n] = lo + hi;
            }
        }
        __syncthreads();

        // reduce 8 partials + xproj + tanh, write h_s
#pragma unroll
        for (int u = 0; u < 4; u++) {
            int idx = t + u * 256;
            int m = idx >> 5, n = idx & 31;
            float sum = 0.0f;
#pragma unroll
            for (int g = 0; g < 8; g++) sum += Rs[(g * 32 + m) * 33 + n];
            size_t o = (size_t)(m0 + m) * HID + (n0 + n);
            outp[o] = tanhf(outp[o] + sum);
        }
        __threadfence();
        __syncthreads();  // all writes fenced before the group arrival

        if (t == 0) {
            atomicAdd(&g_bar[mi], 1u);
            unsigned target = 32u * (unsigned)(s + 1);
            while (atomicAdd(&g_bar[mi], 0u) < target) {
            }
        }
        __syncthreads();  // whole block proceeds only after group barrier
    }
}

// ---------------- kernel 3: FC1 split-K partials (fma2, batch-pair packed) ----------------
__global__ __launch_bounds__(256) void fc1_kernel(const float* __restrict__ W1) {
    __shared__ float Hs[32][130];    // transposed [k][b]
    __shared__ float2 Wp[FC1N][34];  // duplicated {w,w}
    int s = blockIdx.x;
    int t = threadIdx.x;
    const float* src = g_seq + (size_t)s * BATCH * HID;
    int tb = t & 63, tf = t >> 6;

    unsigned long long acc[25];
#pragma unroll
    for (int j = 0; j < 25; j++) acc[j] = 0ull;

    unsigned hBase = smem_u32(&Hs[0][0]) + (unsigned)(2 * tb) * 4u;
    unsigned wBase = smem_u32(&Wp[0][0]) + (unsigned)(tf * 25) * 34u * 8u;

    for (int k0 = 0; k0 < HID; k0 += 32) {
#pragma unroll
        for (int q = 0; q < 4; q++) {
            int f4 = t + q * 256;
            int row = f4 >> 3, c4 = f4 & 7;
            float4 v = *(const float4*)(src + (size_t)row * HID + k0 + c4 * 4);
            Hs[c4 * 4 + 0][row] = v.x;
            Hs[c4 * 4 + 1][row] = v.y;
            Hs[c4 * 4 + 2][row] = v.z;
            Hs[c4 * 4 + 3][row] = v.w;
        }
        for (int f4 = t; f4 < FC1N * 8; f4 += 256) {
            int row = f4 >> 3, c4 = f4 & 7;
            float4 v = *(const float4*)(W1 + (size_t)row * (SEQ * HID) + (size_t)s * HID +
                                        k0 + c4 * 4);
            Wp[row][c4 * 4 + 0] = make_float2(v.x, v.x);
            Wp[row][c4 * 4 + 1] = make_float2(v.y, v.y);
            Wp[row][c4 * 4 + 2] = make_float2(v.z, v.z);
            Wp[row][c4 * 4 + 3] = make_float2(v.w, v.w);
        }
        __syncthreads();
#pragma unroll 4
        for (int k = 0; k < 32; k++) {
            unsigned long long h2 = lds64(hBase + (unsigned)(k * 130) * 4u);
#pragma unroll
            for (int j = 0; j < 25; j++) {
                unsigned long long wv = lds64(wBase + (unsigned)(j * 34 + k) * 8u);
                fma2(acc[j], h2, wv);
            }
        }
        __syncthreads();
    }
    float* dst = g_part + (size_t)s * BATCH * FC1N;
#pragma unroll
    for (int j = 0; j < 25; j++) {
        float lo, hi;
        unpack2(acc[j], lo, hi);
        dst[(size_t)(2 * tb) * FC1N + tf * 25 + j] = lo;
        dst[(size_t)(2 * tb + 1) * FC1N + tf * 25 + j] = hi;
    }
}

// ---------------- kernel 4: deterministic reduce + bias + relu ----------------
__global__ __launch_bounds__(256) void reduce_kernel(const float* __restrict__ b1) {
    int i = blockIdx.x * 256 + threadIdx.x;
    if (i >= BATCH * FC1N) return;
    int f = i % FC1N;
    float p0 = 0.0f, p1 = 0.0f;
    for (int s = 0; s < SEQ; s += 2) {
        p0 += g_part[(size_t)s * BATCH * FC1N + i];
        p1 += g_part[(size_t)(s + 1) * BATCH * FC1N + i];
    }
    g_h1[i] = fmaxf(b1[f] + p0 + p1, 0.0f);
}

// ---------------- kernel 5: FC2 + log_softmax ----------------
__global__ __launch_bounds__(128) void fc2_kernel(const float* __restrict__ W2,
                                                  const float* __restrict__ b2,
                                                  float* __restrict__ out) {
    __shared__ float sW2[NCLS * FC1N];
    int t = threadIdx.x;
    for (int i = t; i < NCLS * FC1N; i += 128) sW2[i] = W2[i];
    __syncthreads();

    float hv[FC1N];
#pragma unroll
    for (int f = 0; f < FC1N; f++) hv[f] = g_h1[(size_t)t * FC1N + f];

    float logits[NCLS];
#pragma unroll
    for (int c = 0; c < NCLS; c++) {
        float acc = b2[c];
#pragma unroll
        for (int f = 0; f < FC1N; f++) acc += hv[f] * sW2[c * FC1N + f];
        logits[c] = acc;
    }
    float m = logits[0];
#pragma unroll
    for (int c = 1; c < NCLS; c++) m = fmaxf(m, logits[c]);
    float sum = 0.0f;
#pragma unroll
    for (int c = 0; c < NCLS; c++) sum += expf(logits[c] - m);
    float lse = m + logf(sum);
#pragma unroll
    for (int c = 0; c < NCLS; c++) out[(size_t)t * NCLS + c] = logits[c] - lse;
}

// ---------------- launch ----------------
extern "C" void kernel_launch(void* const* d_in, const int* in_sizes, int n_in,
                              void* d_out, int out_size) {
    const float* x = (const float*)d_in[0];
    const float* h0 = (const float*)d_in[1];
    const float* Wih = (const float*)d_in[2];
    const float* Whh = (const float*)d_in[3];
    const float* bih = (const float*)d_in[4];
    const float* bhh = (const float*)d_in[5];
    const float* W1 = (const float*)d_in[6];
    const float* b1 = (const float*)d_in[7];
    const float* W2 = (const float*)d_in[8];
    const float* b2 = (const float*)d_in[9];
    float* out = (float*)d_out;
    (void)in_sizes; (void)n_in; (void)out_size;

    cudaFuncSetAttribute(rnn_persist, cudaFuncAttributeMaxDynamicSharedMemorySize,
                         PK_SMEM);

    xproj_kernel<<<dim3(HID / XP_BN, (SEQ * BATCH) / XP_BM), 256>>>(x, Wih, bih, bhh);
    rnn_persist<<<dim3(32, 4), 256, PK_SMEM>>>(h0, Whh);
    fc1_kernel<<<SEQ, 256>>>(W1);
    reduce_kernel<<<(BATCH * FC1N + 255) / 256, 256>>>(b1);
    fc2_kernel<<<1, 128>>>(W2, b2, out);
}